// round 7
// baseline (speedup 1.0000x reference)
#include <cuda_runtime.h>

#define OUT_CH 16
#define PH 7
#define PW 7
#define SR 2
#define HH 80
#define WW 80
#define PLANE_ELEMS (HH * WW)            // 6400 floats
#define NPLANE (OUT_CH * PH * PW)        // 784 channels per batch
#define N_ROIS 512
#define NB 4
#define TPB 256
#define SM_STRIDE 84                      // padded row stride (mult of 4)

// scratch (no allocation allowed)
__device__ float g_params[N_ROIS * 4];    // x1, y1, bh, bw
__device__ int   g_perm[N_ROIS];          // rois sorted by batch
__device__ int   g_boff[NB + 1];          // batch list offsets

// ── Kernel A: per-roi params + counting sort by batch ───────────────────
__global__ void __launch_bounds__(N_ROIS)
roi_prep_kernel(const float* __restrict__ rois) {
    __shared__ int s_cnt[NB];
    __shared__ int s_base[NB];
    const int t = threadIdx.x;
    if (t < NB) s_cnt[t] = 0;
    __syncthreads();

    const float* r = rois + (size_t)t * 5;
    const int   b  = (int)r[0];
    const float x1 = r[1] * (float)WW;
    const float y1 = r[2] * (float)HH;
    const float x2 = r[3] * (float)WW;
    const float y2 = r[4] * (float)HH;
    float* p = g_params + (size_t)t * 4;
    p[0] = x1;
    p[1] = y1;
    p[2] = fmaxf(y2 - y1, 0.1f) * (1.0f / (float)PH);
    p[3] = fmaxf(x2 - x1, 0.1f) * (1.0f / (float)PW);

    const int rank = atomicAdd(&s_cnt[b], 1);
    __syncthreads();
    if (t == 0) {
        int acc = 0;
        for (int i = 0; i < NB; i++) { s_base[i] = acc; g_boff[i] = acc; acc += s_cnt[i]; }
        g_boff[NB] = acc;
    }
    __syncthreads();
    g_perm[s_base[b] + rank] = t;

    // encode batch index of each roi into perm? not needed: block derives b.
}

// ── Kernel B: one block per (batch, channel) plane ──────────────────────
__global__ void __launch_bounds__(TPB)
psroi_align_kernel(const float* __restrict__ feat,
                   float* __restrict__ out) {
    __shared__ float s_plane[HH * SM_STRIDE];   // 26.88 KB

    const int bid = blockIdx.x;
    const int b   = bid / NPLANE;               // batch
    const int idx = bid - b * NPLANE;           // channel = co*49 + ph*7 + pw
    const int rem = idx % (PH * PW);
    const int ph  = rem / PW;
    const int pw  = rem - ph * PW;
    const int tid = threadIdx.x;

    // stream this plane into SMEM (coalesced float4)
    const float* plane = feat + ((size_t)b * NPLANE + (size_t)idx) * PLANE_ELEMS;
    const float4* src = (const float4*)plane;
    #pragma unroll
    for (int k = tid; k < PLANE_ELEMS / 4; k += TPB) {
        float4 v = __ldg(src + k);
        int row = k / (WW / 4);                 // 20 float4 per row
        int col = (k - row * (WW / 4)) * 4;
        *(float4*)&s_plane[row * SM_STRIDE + col] = v;
    }

    const int off = g_boff[b];
    const int cnt = g_boff[b + 1] - off;
    __syncthreads();

    // tasks: (roi, sample) pairs; 4 lanes per output combine via shfl
    const int nt  = cnt * 4;
    const int ntr = ((nt + TPB - 1) / TPB) * TPB;
    for (int t = tid; t < ntr; t += TPB) {
        const int g = t >> 2;                   // roi within batch list
        const int s = t & 3;                    // sample point
        const bool valid = g < cnt;
        const int slot = off + (valid ? g : cnt - 1);
        const int n = g_perm[slot];

        const float* p = g_params + (size_t)n * 4;
        const float x1 = __ldg(p + 0);
        const float y1 = __ldg(p + 1);
        const float bh = __ldg(p + 2);
        const float bw = __ldg(p + 3);

        const float fy = (s & 2) ? 0.75f : 0.25f;
        const float fx = (s & 1) ? 0.75f : 0.25f;
        const float y  = y1 + ((float)ph + fy) * bh;
        const float x  = x1 + ((float)pw + fx) * bw;

        // mask on UNCLIPPED coords (matches reference)
        const float m = (y >= -1.0f && y <= (float)HH &&
                         x >= -1.0f && x <= (float)WW) ? 1.0f : 0.0f;

        const float yc = fminf(fmaxf(y, 0.0f), (float)(HH - 1));
        const float xc = fminf(fmaxf(x, 0.0f), (float)(WW - 1));
        const int y0  = (int)yc;                // yc >= 0 -> floor == trunc
        const int x0  = (int)xc;
        const int y1i = min(y0 + 1, HH - 1);
        const int x1i = min(x0 + 1, WW - 1);
        const float ly = yc - (float)y0, lx = xc - (float)x0;
        const float hy = 1.0f - ly,      hx = 1.0f - lx;

        const float* r0 = s_plane + y0  * SM_STRIDE;
        const float* r1 = s_plane + y1i * SM_STRIDE;
        const float v00 = r0[x0];
        const float v01 = r0[x1i];
        const float v10 = r1[x0];
        const float v11 = r1[x1i];

        float v = m * (hy * (hx * v00 + lx * v01) + ly * (hx * v10 + lx * v11));

        // combine the 4 sample points of this output (lanes differ only in s)
        v += __shfl_xor_sync(0xffffffffu, v, 1);
        v += __shfl_xor_sync(0xffffffffu, v, 2);

        if (valid && s == 0)
            out[(size_t)n * NPLANE + idx] = v * (1.0f / (SR * SR));
    }
}

extern "C" void kernel_launch(void* const* d_in, const int* in_sizes, int n_in,
                              void* d_out, int out_size) {
    const float* feat = (const float*)d_in[0];
    const float* rois = (const float*)d_in[1];
    float* out = (float*)d_out;
    roi_prep_kernel<<<1, N_ROIS>>>(rois);
    psroi_align_kernel<<<NB * NPLANE, TPB>>>(feat, out);
}

// round 8
// speedup vs baseline: 1.0017x; 1.0017x over previous
#include <cuda_runtime.h>
#include <cstdint>

#define OUT_CH 16
#define PH 7
#define PW 7
#define SR 2
#define HH 80
#define WW 80
#define PLANE_ELEMS (HH * WW)            // 6400 floats
#define PLANE_BYTES (PLANE_ELEMS * 4)    // 25600 B
#define NPLANE (OUT_CH * PH * PW)        // 784 channels per batch
#define N_ROIS 512
#define NB 4
#define TPB 256

// scratch (no allocation allowed)
__device__ float g_params[N_ROIS * 4];    // x1, y1, bh, bw
__device__ int   g_perm[N_ROIS];          // rois sorted by batch
__device__ int   g_boff[NB + 1];          // batch list offsets

__device__ __forceinline__ uint32_t smem_u32(const void* p) {
    uint32_t a;
    asm("{ .reg .u64 t; cvta.to.shared.u64 t, %1; cvt.u32.u64 %0, t; }"
        : "=r"(a) : "l"(p));
    return a;
}

// ── Kernel A: per-roi params + counting sort by batch ───────────────────
__global__ void __launch_bounds__(N_ROIS)
roi_prep_kernel(const float* __restrict__ rois) {
    __shared__ int s_cnt[NB];
    __shared__ int s_base[NB];
    const int t = threadIdx.x;
    if (t < NB) s_cnt[t] = 0;
    __syncthreads();

    const float* r = rois + (size_t)t * 5;
    const int   b  = (int)r[0];
    const float x1 = r[1] * (float)WW;
    const float y1 = r[2] * (float)HH;
    const float x2 = r[3] * (float)WW;
    const float y2 = r[4] * (float)HH;
    float* p = g_params + (size_t)t * 4;
    p[0] = x1;
    p[1] = y1;
    p[2] = fmaxf(y2 - y1, 0.1f) * (1.0f / (float)PH);
    p[3] = fmaxf(x2 - x1, 0.1f) * (1.0f / (float)PW);

    const int rank = atomicAdd(&s_cnt[b], 1);
    __syncthreads();
    if (t == 0) {
        int acc = 0;
        for (int i = 0; i < NB; i++) { s_base[i] = acc; g_boff[i] = acc; acc += s_cnt[i]; }
        g_boff[NB] = acc;
    }
    __syncthreads();
    g_perm[s_base[b] + rank] = t;
}

// ── Kernel B: one block per (batch, channel) plane; TMA bulk load ───────
__global__ void __launch_bounds__(TPB)
psroi_align_kernel(const float* __restrict__ feat,
                   float* __restrict__ out) {
    __shared__ alignas(16) float s_plane[PLANE_ELEMS];   // 25.6 KB, linear
    __shared__ alignas(8)  uint64_t s_mbar;

    const int bid = blockIdx.x;
    const int b   = bid / NPLANE;               // batch
    const int idx = bid - b * NPLANE;           // channel = co*49 + ph*7 + pw
    const int rem = idx % (PH * PW);
    const int ph  = rem / PW;
    const int pw  = rem - ph * PW;
    const int tid = threadIdx.x;

    const uint32_t mbar = smem_u32(&s_mbar);
    const uint32_t dst  = smem_u32(s_plane);

    if (tid == 0) {
        asm volatile("mbarrier.init.shared.b64 [%0], 1;" :: "r"(mbar) : "memory");
        asm volatile("fence.proxy.async.shared::cta;" ::: "memory");
    }
    __syncthreads();

    if (tid == 0) {
        const float* src = feat + ((size_t)b * NPLANE + (size_t)idx) * PLANE_ELEMS;
        asm volatile("mbarrier.arrive.expect_tx.shared.b64 _, [%0], %1;"
                     :: "r"(mbar), "r"((uint32_t)PLANE_BYTES) : "memory");
        asm volatile(
            "cp.async.bulk.shared::cta.global.mbarrier::complete_tx::bytes "
            "[%0], [%1], %2, [%3];"
            :: "r"(dst), "l"(src), "r"((uint32_t)PLANE_BYTES), "r"(mbar)
            : "memory");
    }

    // hoist roi-list metadata while TMA runs
    const int off = g_boff[b];
    const int cnt = g_boff[b + 1] - off;

    // wait for the bulk copy (acquire orders smem reads after TMA writes)
    {
        uint32_t done;
        asm volatile(
            "{\n\t.reg .pred p;\n\t"
            "mbarrier.try_wait.parity.acquire.cta.shared::cta.b64 p, [%1], 0;\n\t"
            "selp.b32 %0, 1, 0, p;\n\t}"
            : "=r"(done) : "r"(mbar) : "memory");
        if (!done) {
            asm volatile(
                "{\n\t.reg .pred P1;\n\t"
                "WAIT_LOOP_%=:\n\t"
                "mbarrier.try_wait.parity.acquire.cta.shared::cta.b64 P1, [%0], 0, 0x989680;\n\t"
                "@P1 bra.uni WAIT_DONE_%=;\n\t"
                "bra.uni WAIT_LOOP_%=;\n\t"
                "WAIT_DONE_%=:\n\t}"
                :: "r"(mbar) : "memory");
        }
    }

    // tasks: (roi, sample) pairs; 4 lanes per output combine via shfl
    const int nt  = cnt * 4;
    const int ntr = ((nt + TPB - 1) / TPB) * TPB;
    for (int t = tid; t < ntr; t += TPB) {
        const int g = t >> 2;                   // roi within batch list
        const int s = t & 3;                    // sample point
        const bool valid = g < cnt;
        const int slot = off + (valid ? g : cnt - 1);
        const int n = g_perm[slot];

        const float* p = g_params + (size_t)n * 4;
        const float x1 = __ldg(p + 0);
        const float y1 = __ldg(p + 1);
        const float bh = __ldg(p + 2);
        const float bw = __ldg(p + 3);

        const float fy = (s & 2) ? 0.75f : 0.25f;
        const float fx = (s & 1) ? 0.75f : 0.25f;
        const float y  = y1 + ((float)ph + fy) * bh;
        const float x  = x1 + ((float)pw + fx) * bw;

        // mask on UNCLIPPED coords (matches reference)
        const float m = (y >= -1.0f && y <= (float)HH &&
                         x >= -1.0f && x <= (float)WW) ? 1.0f : 0.0f;

        const float yc = fminf(fmaxf(y, 0.0f), (float)(HH - 1));
        const float xc = fminf(fmaxf(x, 0.0f), (float)(WW - 1));
        const int y0  = (int)yc;                // yc >= 0 -> floor == trunc
        const int x0  = (int)xc;
        const int y1i = min(y0 + 1, HH - 1);
        const int x1i = min(x0 + 1, WW - 1);
        const float ly = yc - (float)y0, lx = xc - (float)x0;
        const float hy = 1.0f - ly,      hx = 1.0f - lx;

        const float* r0 = s_plane + y0  * WW;
        const float* r1 = s_plane + y1i * WW;
        const float v00 = r0[x0];
        const float v01 = r0[x1i];
        const float v10 = r1[x0];
        const float v11 = r1[x1i];

        float v = m * (hy * (hx * v00 + lx * v01) + ly * (hx * v10 + lx * v11));

        v += __shfl_xor_sync(0xffffffffu, v, 1);
        v += __shfl_xor_sync(0xffffffffu, v, 2);

        if (valid && s == 0)
            out[(size_t)n * NPLANE + idx] = v * (1.0f / (SR * SR));
    }
}

extern "C" void kernel_launch(void* const* d_in, const int* in_sizes, int n_in,
                              void* d_out, int out_size) {
    const float* feat = (const float*)d_in[0];
    const float* rois = (const float*)d_in[1];
    float* out = (float*)d_out;
    roi_prep_kernel<<<1, N_ROIS>>>(rois);
    psroi_align_kernel<<<NB * NPLANE, TPB>>>(feat, out);
}